// round 2
// baseline (speedup 1.0000x reference)
#include <cuda_runtime.h>
#include <cstdint>

// out(4096,128) = input(4096,49998) @ word2vecs[0:49998](49998,128), fp32.
// Path: tf32 mma.sync (sm_80 baseline PTX - tcgen05 is unavailable because the
// harness builds PTX at target compute_103, which rejects all 'a'-suffix features).
#define KDIM 49998
#define MDIM 4096
#define NDIM 128
#define SPLITS 9
#define KSPLIT 5568            // 174*32 ; 9*5568 = 50112 >= 49998
#define BM 128
#define BN 128
#define BK 32
#define STAGES 3
#define A_ROWSTRIDE 36         // 32 + 4 pad (floats) -> conflict-free frag reads
#define B_ROWSTRIDE 132        // 128 + 4 pad
#define A_BYTES (BM * A_ROWSTRIDE * 4)      // 18432
#define B_BYTES (BK * B_ROWSTRIDE * 4)      // 16896
#define STAGE_BYTES (A_BYTES + B_BYTES)     // 35328
#define SMEM_TOTAL (STAGES * STAGE_BYTES)   // 105984 -> 2 CTAs/SM

__device__ float g_part[(size_t)SPLITS * MDIM * NDIM];   // split-K partials (18.9 MB)

// ---------------- helpers ----------------
__device__ __forceinline__ uint32_t smem_u32(const void* p) {
    uint32_t a;
    asm("{ .reg .u64 t; cvta.to.shared.u64 t, %1; cvt.u32.u64 %0, t; }" : "=r"(a) : "l"(p));
    return a;
}
__device__ __forceinline__ void cp8(uint32_t dst, const void* src, uint32_t nbytes) {
    asm volatile("cp.async.ca.shared.global [%0], [%1], 8, %2;" :: "r"(dst), "l"(src), "r"(nbytes));
}
__device__ __forceinline__ void cp16(uint32_t dst, const void* src, uint32_t nbytes) {
    asm volatile("cp.async.cg.shared.global [%0], [%1], 16, %2;" :: "r"(dst), "l"(src), "r"(nbytes));
}
__device__ __forceinline__ void cp_commit() { asm volatile("cp.async.commit_group;" ::: "memory"); }
__device__ __forceinline__ void cp_wait1() { asm volatile("cp.async.wait_group 1;" ::: "memory"); }
__device__ __forceinline__ void cp_wait0() { asm volatile("cp.async.wait_group 0;" ::: "memory"); }

__device__ __forceinline__ uint32_t f2tf32(float x) {
    uint32_t r;
    asm("cvt.rna.tf32.f32 %0, %1;" : "=r"(r) : "f"(x));
    return r;
}
__device__ __forceinline__ void mma_m16n8k8(float* c, const uint32_t* a, const uint32_t* b) {
    asm volatile(
        "mma.sync.aligned.m16n8k8.row.col.f32.tf32.tf32.f32 "
        "{%0,%1,%2,%3}, {%4,%5,%6,%7}, {%8,%9}, {%0,%1,%2,%3};"
        : "+f"(c[0]), "+f"(c[1]), "+f"(c[2]), "+f"(c[3])
        : "r"(a[0]), "r"(a[1]), "r"(a[2]), "r"(a[3]), "r"(b[0]), "r"(b[1]));
}

// ---------------- GEMM: tf32 mma.sync, split-K to partials ----------------
__global__ void __launch_bounds__(256, 2) gemm_tf32(const float* __restrict__ A,
                                                    const float* __restrict__ Bg) {
    extern __shared__ float smem[];
    const uint32_t sb = smem_u32(smem);
    const int tid = threadIdx.x;
    const int wid = tid >> 5, lane = tid & 31;
    const int lr = lane >> 2, lk = lane & 3;

    const int m0 = blockIdx.x * BM;
    const int split = blockIdx.y;
    const int klo = split * KSPLIT;
    const int khi = min(KDIM, klo + KSPLIT);
    const int iters = (khi - klo + BK - 1) / BK;

    const int wm = (wid & 1) * 64;   // warp M offset within CTA tile
    const int wc = (wid >> 1) * 32;  // warp N offset

    float acc[4][4][4];
#pragma unroll
    for (int mi = 0; mi < 4; mi++)
#pragma unroll
        for (int ni = 0; ni < 4; ni++)
#pragma unroll
            for (int q = 0; q < 4; q++) acc[mi][ni][q] = 0.f;

    auto load_stage = [&](int stage) {
        const int b = stage % STAGES;
        const uint32_t abase = sb + b * STAGE_BYTES;
        const uint32_t bbase = abase + A_BYTES;
        const int k0 = klo + stage * BK;
        // A tile: 128 rows x 32 floats, 8B granules (A rows only 8B-aligned)
#pragma unroll
        for (int j = 0; j < 8; j++) {
            int G = tid + j * 256;
            int r = G >> 4, g = G & 15;
            int kk = k0 + g * 2;
            const float* src = A + (size_t)(m0 + r) * KDIM + kk;
            uint32_t n = (kk < khi) ? 8u : 0u;
            if (!n) src = A;
            cp8(abase + (uint32_t)(r * A_ROWSTRIDE + g * 2) * 4u, src, n);
        }
        // B tile: 32 rows x 128 floats, 16B granules, native layout (k-major rows)
#pragma unroll
        for (int j = 0; j < 4; j++) {
            int G = tid + j * 256;
            int r = G >> 5, g = G & 31;
            int kk = k0 + r;
            const float* src = Bg + (size_t)kk * NDIM + g * 4;
            uint32_t n = (kk < khi) ? 16u : 0u;
            if (!n) src = Bg;
            cp16(bbase + (uint32_t)(r * B_ROWSTRIDE + g * 4) * 4u, src, n);
        }
        cp_commit();
    };

    load_stage(0);
    if (iters > 1) load_stage(1);

    for (int i = 0; i < iters; i++) {
        if (i + 2 < iters) cp_wait1(); else cp_wait0();
        __syncthreads();
        if (i + 2 < iters) load_stage(i + 2);

        const float* As = smem + (i % STAGES) * (STAGE_BYTES / 4);
        const float* Bs = As + (A_BYTES / 4);

#pragma unroll
        for (int ks = 0; ks < 4; ks++) {
            const int k = ks * 8 + lk;
            uint32_t a[4][4], bfr[4][2];
#pragma unroll
            for (int mi = 0; mi < 4; mi++) {
                int m = wm + mi * 16 + lr;
                a[mi][0] = f2tf32(As[m * A_ROWSTRIDE + k]);
                a[mi][1] = f2tf32(As[(m + 8) * A_ROWSTRIDE + k]);
                a[mi][2] = f2tf32(As[m * A_ROWSTRIDE + k + 4]);
                a[mi][3] = f2tf32(As[(m + 8) * A_ROWSTRIDE + k + 4]);
            }
#pragma unroll
            for (int ni = 0; ni < 4; ni++) {
                int n = wc + ni * 8 + lr;
                bfr[ni][0] = f2tf32(Bs[k * B_ROWSTRIDE + n]);
                bfr[ni][1] = f2tf32(Bs[(k + 4) * B_ROWSTRIDE + n]);
            }
#pragma unroll
            for (int mi = 0; mi < 4; mi++)
#pragma unroll
                for (int ni = 0; ni < 4; ni++)
                    mma_m16n8k8(acc[mi][ni], a[mi], bfr[ni]);
        }
    }

    // epilogue: write per-split partials (deterministic; no float atomics)
    float* base = g_part + (size_t)split * MDIM * NDIM;
#pragma unroll
    for (int mi = 0; mi < 4; mi++) {
        int r0 = m0 + wm + mi * 16 + lr;
#pragma unroll
        for (int ni = 0; ni < 4; ni++) {
            int c0 = wc + ni * 8 + 2 * lk;
            float2 v01 = make_float2(acc[mi][ni][0], acc[mi][ni][1]);
            float2 v23 = make_float2(acc[mi][ni][2], acc[mi][ni][3]);
            *reinterpret_cast<float2*>(base + (size_t)r0 * NDIM + c0) = v01;
            *reinterpret_cast<float2*>(base + (size_t)(r0 + 8) * NDIM + c0) = v23;
        }
    }
}

// ---------------- reduce split-K partials ----------------
__global__ void reduce_k(float* __restrict__ out) {
    const int i = blockIdx.x * blockDim.x + threadIdx.x;  // float4 index over 131072
    const float4* p = reinterpret_cast<const float4*>(g_part);
    float4 a = p[i];
#pragma unroll
    for (int s = 1; s < SPLITS; s++) {
        float4 b = p[(size_t)s * (MDIM * NDIM / 4) + i];
        a.x += b.x; a.y += b.y; a.z += b.z; a.w += b.w;
    }
    reinterpret_cast<float4*>(out)[i] = a;
}

// ---------------- launch ----------------
extern "C" void kernel_launch(void* const* d_in, const int* in_sizes, int n_in,
                              void* d_out, int out_size) {
    const float* input = (const float*)d_in[0];
    const float* w2v   = (const float*)d_in[1];
    if (n_in >= 2 && in_sizes[0] == 50000 * 128) {  // defensive: identify by size
        input = (const float*)d_in[1];
        w2v   = (const float*)d_in[0];
    }
    cudaFuncSetAttribute(gemm_tf32, cudaFuncAttributeMaxDynamicSharedMemorySize, SMEM_TOTAL);

    gemm_tf32<<<dim3(MDIM / BM, SPLITS), 256, SMEM_TOTAL>>>(input, w2v);
    reduce_k<<<(MDIM * NDIM / 4) / 256, 256>>>((float*)d_out);
}